// round 16
// baseline (speedup 1.0000x reference)
#include <cuda_runtime.h>
#include <cuda_bf16.h>
#include <cstdint>

#define BATCH 16
#define NN 2048
#define DD 256

// ---------------- scratch (static device globals; no allocs) ----------------
__device__ __nv_bfloat16 d_Mhi[DD * DD];
__device__ __nv_bfloat16 d_Mlo[DD * DD];
__device__ __nv_bfloat16 d_Ghi[BATCH * NN * DD];
__device__ __nv_bfloat16 d_Glo[BATCH * NN * DD];
__device__ __nv_bfloat16 d_Xhi[BATCH * NN * DD];
__device__ __nv_bfloat16 d_Xlo[BATCH * NN * DD];
__device__ __nv_bfloat16 d_Xthi[BATCH * DD * NN];
__device__ __nv_bfloat16 d_Xtlo[BATCH * DD * NN];
__device__ float d_S[(size_t)BATCH * NN * NN];            // 256 MiB scores
__device__ float d_pm[(size_t)BATCH * NN * 32];
__device__ float d_pl[(size_t)BATCH * NN * 32];
__device__ float d_rm[BATCH * NN];
__device__ float d_rl[BATCH * NN];

// ---------------- helpers ----------------
__device__ __forceinline__ uint32_t smem_to_u32(const void* p) {
    uint32_t a;
    asm("{ .reg .u64 t; cvta.to.shared.u64 t, %1; cvt.u32.u64 %0, t; }" : "=r"(a) : "l"(p));
    return a;
}
__device__ __forceinline__ void split_hl(float v, float& h, float& l) {
    __nv_bfloat16 hb = __float2bfloat16(v);
    h = __bfloat162float(hb);
    l = v - h;
}
__device__ __forceinline__ uint32_t pack_bf2(float a, float b) {
    __nv_bfloat162 h = __floats2bfloat162_rn(a, b);
    return *(uint32_t*)&h;
}
__device__ __forceinline__ void ldmx4(uint32_t (&d)[4], uint32_t addr) {
    asm volatile("ldmatrix.sync.aligned.m8n8.x4.shared.b16 {%0,%1,%2,%3}, [%4];"
                 : "=r"(d[0]), "=r"(d[1]), "=r"(d[2]), "=r"(d[3]) : "r"(addr));
}
__device__ __forceinline__ void mma16816(float (&c)[4], const uint32_t (&a)[4],
                                         uint32_t b0, uint32_t b1) {
    asm volatile(
        "mma.sync.aligned.m16n8k16.row.col.f32.bf16.bf16.f32 "
        "{%0,%1,%2,%3}, {%4,%5,%6,%7}, {%8,%9}, {%0,%1,%2,%3};"
        : "+f"(c[0]), "+f"(c[1]), "+f"(c[2]), "+f"(c[3])
        : "r"(a[0]), "r"(a[1]), "r"(a[2]), "r"(a[3]), "r"(b0), "r"(b1));
}
// streaming stores/loads (no L2 allocate priority)
__device__ __forceinline__ void stcs2(float* p, float a, float b) {
    asm volatile("st.global.cs.v2.f32 [%0], {%1, %2};" :: "l"(p), "f"(a), "f"(b) : "memory");
}
__device__ __forceinline__ void stcs4(float* p, float4 v) {
    asm volatile("st.global.cs.v4.f32 [%0], {%1, %2, %3, %4};"
                 :: "l"(p), "f"(v.x), "f"(v.y), "f"(v.z), "f"(v.w) : "memory");
}
__device__ __forceinline__ float4 ldcs4(const float* p) {
    float4 v;
    asm volatile("ld.global.cs.v4.f32 {%0, %1, %2, %3}, [%4];"
                 : "=f"(v.x), "=f"(v.y), "=f"(v.z), "=f"(v.w) : "l"(p));
    return v;
}
__device__ __forceinline__ void cp16(uint32_t dst, const void* src) {
    asm volatile("cp.async.cg.shared.global [%0], [%1], 16;" :: "r"(dst), "l"(src));
}
#define CP_COMMIT() asm volatile("cp.async.commit_group;" ::: "memory")
#define CP_WAIT(n)  asm volatile("cp.async.wait_group %0;" :: "n"(n) : "memory")

// ---- k32 tiles: 64B rows, slot-swizzle: colbyte ^ (((row>>1)&3)<<4) ----
template <int ROWS>
__device__ __forceinline__ void stage32(uint32_t dst, const __nv_bfloat16* src,
                                        int stride, int tid) {
#pragma unroll
    for (int p = 0; p < ROWS / 64; ++p) {
        int i = tid + p * 256;
        int r = i >> 2, c = (i & 3) << 4;
        cp16(dst + (uint32_t)(r * 64 + (c ^ (((r >> 1) & 3) << 4))),
             src + (size_t)r * stride + (c >> 1));
    }
}
__device__ __forceinline__ uint32_t tile_addr64(uint32_t base, int rowbase, int kb, int lane) {
    int mat = lane >> 3, ri = lane & 7;
    int row = rowbase + (mat & 1) * 8 + ri;
    int colb = kb + (mat >> 1) * 16;
    return base + (uint32_t)(row * 64 + (colb ^ (((row >> 1) & 3) << 4)));
}

// Warp computes 32x64 over one k=32 chunk, 3 passes.
__device__ __forceinline__ void mma_chunk3_32(float (&acc)[2][8][4],
                                              uint32_t aHi, uint32_t aLo,
                                              uint32_t bHi, uint32_t bLo,
                                              int mrow, int ncol, int lane) {
#pragma unroll
    for (int k16 = 0; k16 < 2; ++k16) {
        int kb = k16 * 32;
        uint32_t ah[2][4], al[2][4];
        ldmx4(ah[0], tile_addr64(aHi, mrow, kb, lane));
        ldmx4(ah[1], tile_addr64(aHi, mrow + 16, kb, lane));
        ldmx4(al[0], tile_addr64(aLo, mrow, kb, lane));
        ldmx4(al[1], tile_addr64(aLo, mrow + 16, kb, lane));
#pragma unroll
        for (int gp = 0; gp < 4; gp += 2) {
            uint32_t b0[4], b1[4];
            ldmx4(b0, tile_addr64(bHi, ncol + gp * 16, kb, lane));
            ldmx4(b1, tile_addr64(bHi, ncol + (gp + 1) * 16, kb, lane));
#pragma unroll
            for (int mi = 0; mi < 2; ++mi) {
                mma16816(acc[mi][gp * 2 + 0], ah[mi], b0[0], b0[2]);
                mma16816(acc[mi][gp * 2 + 1], ah[mi], b0[1], b0[3]);
                mma16816(acc[mi][gp * 2 + 2], ah[mi], b1[0], b1[2]);
                mma16816(acc[mi][gp * 2 + 3], ah[mi], b1[1], b1[3]);
            }
#pragma unroll
            for (int mi = 0; mi < 2; ++mi) {
                mma16816(acc[mi][gp * 2 + 0], al[mi], b0[0], b0[2]);
                mma16816(acc[mi][gp * 2 + 1], al[mi], b0[1], b0[3]);
                mma16816(acc[mi][gp * 2 + 2], al[mi], b1[0], b1[2]);
                mma16816(acc[mi][gp * 2 + 3], al[mi], b1[1], b1[3]);
            }
            uint32_t c0[4], c1[4];
            ldmx4(c0, tile_addr64(bLo, ncol + gp * 16, kb, lane));
            ldmx4(c1, tile_addr64(bLo, ncol + (gp + 1) * 16, kb, lane));
#pragma unroll
            for (int mi = 0; mi < 2; ++mi) {
                mma16816(acc[mi][gp * 2 + 0], ah[mi], c0[0], c0[2]);
                mma16816(acc[mi][gp * 2 + 1], ah[mi], c0[1], c0[3]);
                mma16816(acc[mi][gp * 2 + 2], ah[mi], c1[0], c1[2]);
                mma16816(acc[mi][gp * 2 + 3], ah[mi], c1[1], c1[3]);
            }
        }
    }
}

#define SET32 32768   // one scores/gproj buffer set: Ahi|Alo|Bhi|Blo, 8KB each
#define TPITCH 132    // transposed spill pitch (floats)

// ---------------------------------------------------------------------------
// K1: M = W @ W^T  -> hi/lo bf16
// ---------------------------------------------------------------------------
__global__ void wwt_kernel(const float* __restrict__ W) {
    __shared__ float sR[16][257];
    __shared__ float sC[16][257];
    int tx = threadIdx.x, ty = threadIdx.y;
    int t = ty * 16 + tx;
    int r0 = blockIdx.y * 16, c0 = blockIdx.x * 16;
    {
        int row = t >> 4, base = t & 15;
#pragma unroll
        for (int p = 0; p < 16; ++p) {
            int col = base + p * 16;
            sR[row][col] = W[(r0 + row) * DD + col];
            sC[row][col] = W[(c0 + row) * DD + col];
        }
    }
    __syncthreads();
    float acc = 0.f;
#pragma unroll 8
    for (int k = 0; k < DD; ++k) acc += sR[ty][k] * sC[tx][k];
    float h, l;
    split_hl(acc, h, l);
    d_Mhi[(r0 + ty) * DD + (c0 + tx)] = __float2bfloat16(h);
    d_Mlo[(r0 + ty) * DD + (c0 + tx)] = __float2bfloat16(l);
}

// ---------------------------------------------------------------------------
// K2: X -> Xhi/Xlo (row-major) + Xthi/Xtlo ([b][d][m])
// ---------------------------------------------------------------------------
__global__ __launch_bounds__(256) void convx_kernel(const float* __restrict__ X) {
    __shared__ float tile[32][33];
    int b = blockIdx.z;
    int m0 = blockIdx.y * 32, d0 = blockIdx.x * 32;
    int j = threadIdx.x & 31, i0 = threadIdx.x >> 5;
    const float* Xb = X + (size_t)b * NN * DD;
#pragma unroll
    for (int i = i0; i < 32; i += 8) {
        float v = Xb[(size_t)(m0 + i) * DD + d0 + j];
        tile[i][j] = v;
        float h, l;
        split_hl(v, h, l);
        size_t idx = (size_t)b * NN * DD + (size_t)(m0 + i) * DD + d0 + j;
        d_Xhi[idx] = __float2bfloat16(h);
        d_Xlo[idx] = __float2bfloat16(l);
    }
    __syncthreads();
#pragma unroll
    for (int i = i0; i < 32; i += 8) {
        float v = tile[j][i];
        float h, l;
        split_hl(v, h, l);
        size_t idx = (size_t)b * DD * NN + (size_t)(d0 + i) * NN + m0 + j;
        d_Xthi[idx] = __float2bfloat16(h);
        d_Xtlo[idx] = __float2bfloat16(l);
    }
}

// ---------------------------------------------------------------------------
// K3: G = X @ M.  k32 double-buffered, occ 2 (R9 form).
// ---------------------------------------------------------------------------
__global__ __launch_bounds__(256, 2) void gproj_kernel() {
    extern __shared__ __align__(128) char sm[];
    uint32_t base = smem_to_u32(sm);
    int tid = threadIdx.x, lane = tid & 31, wid = tid >> 5;
    int nh = blockIdx.x, ti = blockIdx.y;
    int mrow = (wid >> 1) * 32, ncol = (wid & 1) * 64;

    float acc[2][8][4];
#pragma unroll
    for (int mi = 0; mi < 2; ++mi)
#pragma unroll
        for (int nf = 0; nf < 8; ++nf)
#pragma unroll
            for (int q = 0; q < 4; ++q) acc[mi][nf][q] = 0.f;

    const __nv_bfloat16* Ahi = d_Xhi + (size_t)ti * 128 * DD;
    const __nv_bfloat16* Alo = d_Xlo + (size_t)ti * 128 * DD;
    const __nv_bfloat16* Bhi = d_Mhi + nh * 128 * DD;
    const __nv_bfloat16* Blo = d_Mlo + nh * 128 * DD;

    stage32<128>(base, Ahi, DD, tid);
    stage32<128>(base + 8192, Alo, DD, tid);
    stage32<128>(base + 16384, Bhi, DD, tid);
    stage32<128>(base + 24576, Blo, DD, tid);
    CP_COMMIT();

    for (int kc = 0; kc < 8; ++kc) {
        if (kc < 7) {
            uint32_t nb = base + ((kc + 1) & 1) * SET32;
            int k0 = (kc + 1) * 32;
            stage32<128>(nb, Ahi + k0, DD, tid);
            stage32<128>(nb + 8192, Alo + k0, DD, tid);
            stage32<128>(nb + 16384, Bhi + k0, DD, tid);
            stage32<128>(nb + 24576, Blo + k0, DD, tid);
            CP_COMMIT();
            CP_WAIT(1);
        } else {
            CP_WAIT(0);
        }
        __syncthreads();
        uint32_t cb = base + (kc & 1) * SET32;
        mma_chunk3_32(acc, cb, cb + 8192, cb + 16384, cb + 24576, mrow, ncol, lane);
        __syncthreads();
    }
#pragma unroll
    for (int mi = 0; mi < 2; ++mi) {
        int rA = ti * 128 + mrow + mi * 16 + (lane >> 2);
        int rB = rA + 8;
#pragma unroll
        for (int nf = 0; nf < 8; ++nf) {
            int col = nh * 128 + ncol + nf * 8 + (lane & 3) * 2;
            float h0, l0, h1, l1;
            split_hl(acc[mi][nf][0], h0, l0);
            split_hl(acc[mi][nf][1], h1, l1);
            *(uint32_t*)&d_Ghi[(size_t)rA * DD + col] = pack_bf2(h0, h1);
            *(uint32_t*)&d_Glo[(size_t)rA * DD + col] = pack_bf2(l0, l1);
            split_hl(acc[mi][nf][2], h0, l0);
            split_hl(acc[mi][nf][3], h1, l1);
            *(uint32_t*)&d_Ghi[(size_t)rB * DD + col] = pack_bf2(h0, h1);
            *(uint32_t*)&d_Glo[(size_t)rB * DD + col] = pack_bf2(l0, l1);
        }
    }
}

// ---------------------------------------------------------------------------
// K4: scores, upper-triangle tiles, k32 double-buffered; R14 epilogue
// (transposed mirror spill) + streaming S stores.
// ---------------------------------------------------------------------------
__global__ __launch_bounds__(256, 2) void scores_kernel(const float* __restrict__ ADJ) {
    extern __shared__ __align__(128) char sm[];
    uint32_t base = smem_to_u32(sm);
    float* sT = (float*)sm;     // transposed spill: sT[c * TPITCH + r]
    int tid = threadIdx.x, lane = tid & 31, wid = tid >> 5;
    int b = blockIdx.y;
    int rt = 0, rem = blockIdx.x;
    while (rem >= 16 - rt) { rem -= 16 - rt; rt++; }
    int nt = rt + rem;
    int mrow = (wid >> 1) * 32, ncol = (wid & 1) * 64;

    float acc[2][8][4];
#pragma unroll
    for (int mi = 0; mi < 2; ++mi)
#pragma unroll
        for (int nf = 0; nf < 8; ++nf)
#pragma unroll
            for (int q = 0; q < 4; ++q) acc[mi][nf][q] = 0.f;

    const __nv_bfloat16* Ahi = d_Ghi + ((size_t)b * NN + rt * 128) * DD;
    const __nv_bfloat16* Alo = d_Glo + ((size_t)b * NN + rt * 128) * DD;
    const __nv_bfloat16* Bhi = d_Xhi + ((size_t)b * NN + nt * 128) * DD;
    const __nv_bfloat16* Blo = d_Xlo + ((size_t)b * NN + nt * 128) * DD;

    stage32<128>(base, Ahi, DD, tid);
    stage32<128>(base + 8192, Alo, DD, tid);
    stage32<128>(base + 16384, Bhi, DD, tid);
    stage32<128>(base + 24576, Blo, DD, tid);
    CP_COMMIT();

    for (int kc = 0; kc < 8; ++kc) {
        if (kc < 7) {
            uint32_t nb = base + ((kc + 1) & 1) * SET32;
            int k0 = (kc + 1) * 32;
            stage32<128>(nb, Ahi + k0, DD, tid);
            stage32<128>(nb + 8192, Alo + k0, DD, tid);
            stage32<128>(nb + 16384, Bhi + k0, DD, tid);
            stage32<128>(nb + 24576, Blo + k0, DD, tid);
            CP_COMMIT();
            CP_WAIT(1);
        } else {
            CP_WAIT(0);
        }
        __syncthreads();
        uint32_t cb = base + (kc & 1) * SET32;
        mma_chunk3_32(acc, cb, cb + 8192, cb + 16384, cb + 24576, mrow, ncol, lane);
        __syncthreads();
    }

    // apply leaky; spill TRANSPOSED into sT[c][r] (pitch 132)
#pragma unroll
    for (int mi = 0; mi < 2; ++mi)
#pragma unroll
        for (int nf = 0; nf < 8; ++nf)
#pragma unroll
            for (int q = 0; q < 4; ++q) {
                int r = mrow + mi * 16 + (lane >> 2) + (q >> 1) * 8;
                int c = ncol + nf * 8 + (lane & 3) * 2 + (q & 1);
                float v = acc[mi][nf][q];
                v = fmaxf(v, 0.2f * v);
                acc[mi][nf][q] = v;
                sT[c * TPITCH + r] = v;
            }
    __syncthreads();

    // ---- original block: fragments -> *adj -> S(.cs) + 64col partials ----
    {
        int cb0 = nt * 128 + ncol + (lane & 3) * 2;
        float mx[2][2] = {{-1e30f, -1e30f}, {-1e30f, -1e30f}};
#pragma unroll
        for (int mi = 0; mi < 2; ++mi) {
            int rA = rt * 128 + mrow + mi * 16 + (lane >> 2);
            int rB = rA + 8;
            const float* adjA = ADJ + ((size_t)b * NN + rA) * NN;
            const float* adjB = ADJ + ((size_t)b * NN + rB) * NN;
            float* swA = d_S + ((size_t)b * NN + rA) * NN;
            float* swB = d_S + ((size_t)b * NN + rB) * NN;
#pragma unroll
            for (int nf = 0; nf < 8; ++nf) {
                int c = cb0 + nf * 8;
                float2 aA = make_float2(__ldcs(&adjA[c]), __ldcs(&adjA[c + 1]));
                float2 aB = make_float2(__ldcs(&adjB[c]), __ldcs(&adjB[c + 1]));
                float v0 = acc[mi][nf][0] * aA.x;
                float v1 = acc[mi][nf][1] * aA.y;
                float v2 = acc[mi][nf][2] * aB.x;
                float v3 = acc[mi][nf][3] * aB.y;
                acc[mi][nf][0] = v0; acc[mi][nf][1] = v1;
                acc[mi][nf][2] = v2; acc[mi][nf][3] = v3;
                stcs2(&swA[c], v0, v1);
                stcs2(&swB[c], v2, v3);
                mx[mi][0] = fmaxf(mx[mi][0], fmaxf(v0, v1));
                mx[mi][1] = fmaxf(mx[mi][1], fmaxf(v2, v3));
            }
        }
#pragma unroll
        for (int mi = 0; mi < 2; ++mi)
#pragma unroll
            for (int h = 0; h < 2; ++h) {
                mx[mi][h] = fmaxf(mx[mi][h], __shfl_xor_sync(0xffffffffu, mx[mi][h], 1));
                mx[mi][h] = fmaxf(mx[mi][h], __shfl_xor_sync(0xffffffffu, mx[mi][h], 2));
            }
        float sum[2][2] = {{0.f, 0.f}, {0.f, 0.f}};
#pragma unroll
        for (int mi = 0; mi < 2; ++mi)
#pragma unroll
            for (int nf = 0; nf < 8; ++nf) {
                sum[mi][0] += __expf(acc[mi][nf][0] - mx[mi][0]) + __expf(acc[mi][nf][1] - mx[mi][0]);
                sum[mi][1] += __expf(acc[mi][nf][2] - mx[mi][1]) + __expf(acc[mi][nf][3] - mx[mi][1]);
            }
#pragma unroll
        for (int mi = 0; mi < 2; ++mi)
#pragma unroll
            for (int h = 0; h < 2; ++h) {
                sum[mi][h] += __shfl_xor_sync(0xffffffffu, sum[mi][h], 1);
                sum[mi][h] += __shfl_xor_sync(0xffffffffu, sum[mi][h], 2);
            }
        if ((lane & 3) == 0) {
            int pi = nt * 2 + (wid & 1);
#pragma unroll
            for (int mi = 0; mi < 2; ++mi)
#pragma unroll
                for (int h = 0; h < 2; ++h) {
                    int row = rt * 128 + mrow + mi * 16 + (lane >> 2) + h * 8;
                    size_t idx = (((size_t)b * NN + row) << 5) + pi;
                    d_pm[idx] = mx[mi][h];
                    d_pl[idx] = sum[mi][h];
                }
        }
    }

    // ---- mirror block (nt > rt): contiguous reads from transposed spill ----
    if (nt > rt) {
        int r = tid >> 1, half = tid & 1;
        int rowg = nt * 128 + r;
        const float* adjp = ADJ + ((size_t)b * NN + rowg) * NN + rt * 128 + half * 64;
        float* sp = d_S + ((size_t)b * NN + rowg) * NN + rt * 128 + half * 64;
        const float* trow = &sT[r * TPITCH + half * 64];
        float mcs[2], scs[2];
#pragma unroll
        for (int cs = 0; cs < 2; ++cs) {
            float v[32];
            float mx = -1e30f;
#pragma unroll
            for (int k = 0; k < 32; k += 4) {
                float4 a = make_float4(__ldcs(&adjp[cs * 32 + k]), __ldcs(&adjp[cs * 32 + k + 1]),
                                       __ldcs(&adjp[cs * 32 + k + 2]), __ldcs(&adjp[cs * 32 + k + 3]));
                float4 sv = *(const float4*)&trow[cs * 32 + k];
                float t0 = sv.x * a.x, t1 = sv.y * a.y, t2 = sv.z * a.z, t3 = sv.w * a.w;
                v[k] = t0; v[k + 1] = t1; v[k + 2] = t2; v[k + 3] = t3;
                mx = fmaxf(mx, fmaxf(fmaxf(t0, t1), fmaxf(t2, t3)));
                stcs4(&sp[cs * 32 + k], make_float4(t0, t1, t2, t3));
            }
            float s = 0.f;
#pragma unroll
            for (int k = 0; k < 32; ++k) s += __expf(v[k] - mx);
            mcs[cs] = mx;
            scs[cs] = s;
        }
        float m = fmaxf(mcs[0], mcs[1]);
        float s = scs[0] * __expf(mcs[0] - m) + scs[1] * __expf(mcs[1] - m);
        size_t idx = (((size_t)(b * NN + rowg)) << 5) + rt * 2 + half;
        d_pm[idx] = m;
        d_pl[idx] = s;
    }
}

// ---------------------------------------------------------------------------
// K5: merge 32 partials -> d_rm, d_rl
// ---------------------------------------------------------------------------
__global__ void reduce_kernel() {
    int i = blockIdx.x * 256 + threadIdx.x;
    const float* pm = d_pm + ((size_t)i << 5);
    const float* pl = d_pl + ((size_t)i << 5);
    float m = -1e30f;
#pragma unroll
    for (int j = 0; j < 32; ++j) m = fmaxf(m, pm[j]);
    float l = 0.f;
#pragma unroll
    for (int j = 0; j < 32; ++j) l += pl[j] * __expf(pm[j] - m);
    d_rm[i] = m;
    d_rl[i] = l;
}

// ---------------------------------------------------------------------------
// K6: PV.  R9 form: 256 threads, k32 double-buffered, occ 2.
// Set layout: Phi 0 | Plo 4K | Xthi 8K | Xtlo 24K  (40KB/set)
// S reads via ld.global.cs (streaming).
// ---------------------------------------------------------------------------
__global__ __launch_bounds__(256, 2) void pv_kernel(const float* __restrict__ bias,
                                                    float* __restrict__ OUT) {
    extern __shared__ __align__(128) char smc[];
    uint32_t base = smem_to_u32(smc);
    int tid = threadIdx.x, lane = tid & 31, wid = tid >> 5;
    int rt = blockIdx.x, b = blockIdx.y;
    int mrow = (wid >> 2) * 32, ncol = (wid & 3) * 64;

    float acc[2][8][4];
#pragma unroll
    for (int mi = 0; mi < 2; ++mi)
#pragma unroll
        for (int nf = 0; nf < 8; ++nf)
#pragma unroll
            for (int q = 0; q < 4; ++q) acc[mi][nf][q] = 0.f;

    const __nv_bfloat16* Bthi = d_Xthi + (size_t)b * DD * NN;
    const __nv_bfloat16* Btlo = d_Xtlo + (size_t)b * DD * NN;

    int pr = tid >> 2, pc = (tid & 3) * 8;
    float mrw = d_rm[b * NN + rt * 64 + pr];
    float linv = 1.f / d_rl[b * NN + rt * 64 + pr];
    const float* sbase = d_S + ((size_t)b * NN + rt * 64 + pr) * NN + pc;
    uint32_t pbyte = (uint32_t)(pr * 64 + (((tid & 3) * 16) ^ (((pr >> 1) & 3) << 4)));

    // prologue: chunk 0
    stage32<256>(base + 8192, Bthi, NN, tid);
    stage32<256>(base + 24576, Btlo, NN, tid);
    CP_COMMIT();
    {
        float p[8];
        float4 s0 = ldcs4(&sbase[0]);
        float4 s1 = ldcs4(&sbase[4]);
        p[0] = __expf(s0.x - mrw) * linv; p[1] = __expf(s0.y - mrw) * linv;
        p[2] = __expf(s0.z - mrw) * linv; p[3] = __expf(s0.w - mrw) * linv;
        p[4] = __expf(s1.x - mrw) * linv; p[5] = __expf(s1.y - mrw) * linv;
        p[6] = __expf(s1.z - mrw) * linv; p[7] = __expf(s1.w - mrw) * linv;
        uint32_t hi[4], lo[4];
#pragma unroll
        for (int q = 0; q < 4; ++q) {
            float h0, l0, h1, l1;
            split_hl(p[2 * q], h0, l0);
            split_hl(p[2 * q + 1], h1, l1);
            hi[q] = pack_bf2(h0, h1);
            lo[q] = pack_bf2(l0, l1);
        }
        *(uint4*)(smc + pbyte) = make_uint4(hi[0], hi[1], hi[2], hi[3]);
        *(uint4*)(smc + 4096 + pbyte) = make_uint4(lo[0], lo[1], lo[2], lo[3]);
    }

    for (int kt = 0; kt < 64; ++kt) {
        if (kt < 63) {
            int nset = (kt + 1) & 1;
            uint32_t nb = base + nset * 40960;
            int k0 = (kt + 1) * 32;
            stage32<256>(nb + 8192, Bthi + k0, NN, tid);
            stage32<256>(nb + 24576, Btlo + k0, NN, tid);
            CP_COMMIT();
            float p[8];
            float4 s0 = ldcs4(&sbase[k0]);
            float4 s1 = ldcs4(&sbase[k0 + 4]);
            p[0] = __expf(s0.x - mrw) * linv; p[1] = __expf(s0.y - mrw) * linv;
            p[2] = __expf(s0.z - mrw) * linv; p[3] = __expf(s0.w - mrw) * linv;
            p[4] = __expf(s1.x - mrw) * linv; p[5] = __expf(s1.y - mrw) * linv;
            p[6] = __expf(s1.z - mrw) * linv; p[7] = __expf(s1.w - mrw) * linv;
            uint32_t hi[4], lo[4];
#pragma unroll
            for (int q = 0; q < 4; ++q) {
                float h0, l0, h1, l1;
                split_hl(p[2 * q], h0, l0);
                split_hl(p[2 * q + 1], h1, l1);
                hi[q] = pack_bf2(h0, h1);
                lo[q] = pack_bf2(l0, l1);
            }
            *(uint4*)(smc + nset * 40960 + pbyte) = make_uint4(hi[0], hi[1], hi[2], hi[3]);
            *(uint4*)(smc + nset * 40960 + 4096 + pbyte) = make_uint4(lo[0], lo[1], lo[2], lo[3]);
            CP_WAIT(1);
        } else {
            CP_WAIT(0);
        }
        __syncthreads();
        uint32_t cb = base + (kt & 1) * 40960;
        mma_chunk3_32(acc, cb, cb + 4096, cb + 8192, cb + 24576, mrow, ncol, lane);
        __syncthreads();
    }

#pragma unroll
    for (int mi = 0; mi < 2; ++mi) {
        int rA = rt * 64 + mrow + mi * 16 + (lane >> 2);
        int rB = rA + 8;
#pragma unroll
        for (int nf = 0; nf < 8; ++nf) {
            int col = ncol + nf * 8 + (lane & 3) * 2;
            float2 bv = *(const float2*)&bias[col];
            *(float2*)&OUT[((size_t)b * NN + rA) * DD + col] =
                make_float2(acc[mi][nf][0] + bv.x, acc[mi][nf][1] + bv.y);
            *(float2*)&OUT[((size_t)b * NN + rB) * DD + col] =
                make_float2(acc[mi][nf][2] + bv.x, acc[mi][nf][3] + bv.y);
        }
    }
}

// ---------------------------------------------------------------------------
extern "C" void kernel_launch(void* const* d_in, const int* in_sizes, int n_in,
                              void* d_out, int out_size) {
    const float* x    = (const float*)d_in[0];
    const float* adj  = (const float*)d_in[1];
    const float* W    = (const float*)d_in[2];
    const float* bias = (const float*)d_in[3];
    float* out = (float*)d_out;

    wwt_kernel<<<dim3(16, 16), dim3(16, 16)>>>(W);
    convx_kernel<<<dim3(8, 64, 16), 256>>>(x);

    const int SMB_G = 2 * SET32;                 // 65536
    const int SMB_S = 128 * TPITCH * 4;          // 67584 (holds buffers + sT)
    const int SMB_P = 81920;                     // 2 x 40KB
    cudaFuncSetAttribute(gproj_kernel, cudaFuncAttributeMaxDynamicSharedMemorySize, SMB_G);
    cudaFuncSetAttribute(scores_kernel, cudaFuncAttributeMaxDynamicSharedMemorySize, SMB_S);
    cudaFuncSetAttribute(pv_kernel, cudaFuncAttributeMaxDynamicSharedMemorySize, SMB_P);

    gproj_kernel<<<dim3(2, 256), 256, SMB_G>>>();
    scores_kernel<<<dim3(136, 16), 256, SMB_S>>>(adj);
    reduce_kernel<<<BATCH * NN / 256, 256>>>();
    pv_kernel<<<dim3(32, 16), 256, SMB_P>>>(bias, out);
}

// round 17
// speedup vs baseline: 1.1458x; 1.1458x over previous
#include <cuda_runtime.h>
#include <cuda_bf16.h>
#include <cstdint>

#define BATCH 16
#define NN 2048
#define DD 256

// ---------------- scratch (static device globals; no allocs) ----------------
__device__ __nv_bfloat16 d_Mhi[DD * DD];
__device__ __nv_bfloat16 d_Mlo[DD * DD];
__device__ __nv_bfloat16 d_Ghi[BATCH * NN * DD];
__device__ __nv_bfloat16 d_Glo[BATCH * NN * DD];
__device__ __nv_bfloat16 d_Xhi[BATCH * NN * DD];
__device__ __nv_bfloat16 d_Xlo[BATCH * NN * DD];
__device__ __nv_bfloat16 d_Xthi[BATCH * DD * NN];
__device__ __nv_bfloat16 d_Xtlo[BATCH * DD * NN];
__device__ float d_S[(size_t)BATCH * NN * NN];            // 256 MiB scores
__device__ float d_pm[(size_t)BATCH * NN * 32];
__device__ float d_pl[(size_t)BATCH * NN * 32];
__device__ float d_rm[BATCH * NN];
__device__ float d_rl[BATCH * NN];

// ---------------- helpers ----------------
__device__ __forceinline__ uint32_t smem_to_u32(const void* p) {
    uint32_t a;
    asm("{ .reg .u64 t; cvta.to.shared.u64 t, %1; cvt.u32.u64 %0, t; }" : "=r"(a) : "l"(p));
    return a;
}
__device__ __forceinline__ void split_hl(float v, float& h, float& l) {
    __nv_bfloat16 hb = __float2bfloat16(v);
    h = __bfloat162float(hb);
    l = v - h;
}
__device__ __forceinline__ uint32_t pack_bf2(float a, float b) {
    __nv_bfloat162 h = __floats2bfloat162_rn(a, b);
    return *(uint32_t*)&h;
}
__device__ __forceinline__ void ldmx4(uint32_t (&d)[4], uint32_t addr) {
    asm volatile("ldmatrix.sync.aligned.m8n8.x4.shared.b16 {%0,%1,%2,%3}, [%4];"
                 : "=r"(d[0]), "=r"(d[1]), "=r"(d[2]), "=r"(d[3]) : "r"(addr));
}
__device__ __forceinline__ void mma16816(float (&c)[4], const uint32_t (&a)[4],
                                         uint32_t b0, uint32_t b1) {
    asm volatile(
        "mma.sync.aligned.m16n8k16.row.col.f32.bf16.bf16.f32 "
        "{%0,%1,%2,%3}, {%4,%5,%6,%7}, {%8,%9}, {%0,%1,%2,%3};"
        : "+f"(c[0]), "+f"(c[1]), "+f"(c[2]), "+f"(c[3])
        : "r"(a[0]), "r"(a[1]), "r"(a[2]), "r"(a[3]), "r"(b0), "r"(b1));
}
__device__ __forceinline__ void cp16(uint32_t dst, const void* src) {
    asm volatile("cp.async.cg.shared.global [%0], [%1], 16;" :: "r"(dst), "l"(src));
}
#define CP_COMMIT() asm volatile("cp.async.commit_group;" ::: "memory")
#define CP_WAIT(n)  asm volatile("cp.async.wait_group %0;" :: "n"(n) : "memory")

// ---- k32 tiles: 64B rows, slot-swizzle: colbyte ^ (((row>>1)&3)<<4) ----
template <int ROWS>
__device__ __forceinline__ void stage32(uint32_t dst, const __nv_bfloat16* src,
                                        int stride, int tid) {
#pragma unroll
    for (int p = 0; p < ROWS / 64; ++p) {
        int i = tid + p * 256;
        int r = i >> 2, c = (i & 3) << 4;
        cp16(dst + (uint32_t)(r * 64 + (c ^ (((r >> 1) & 3) << 4))),
             src + (size_t)r * stride + (c >> 1));
    }
}
__device__ __forceinline__ uint32_t tile_addr64(uint32_t base, int rowbase, int kb, int lane) {
    int mat = lane >> 3, ri = lane & 7;
    int row = rowbase + (mat & 1) * 8 + ri;
    int colb = kb + (mat >> 1) * 16;
    return base + (uint32_t)(row * 64 + (colb ^ (((row >> 1) & 3) << 4)));
}

// Warp computes 32x64 over one k=32 chunk, 3 passes.
__device__ __forceinline__ void mma_chunk3_32(float (&acc)[2][8][4],
                                              uint32_t aHi, uint32_t aLo,
                                              uint32_t bHi, uint32_t bLo,
                                              int mrow, int ncol, int lane) {
#pragma unroll
    for (int k16 = 0; k16 < 2; ++k16) {
        int kb = k16 * 32;
        uint32_t ah[2][4], al[2][4];
        ldmx4(ah[0], tile_addr64(aHi, mrow, kb, lane));
        ldmx4(ah[1], tile_addr64(aHi, mrow + 16, kb, lane));
        ldmx4(al[0], tile_addr64(aLo, mrow, kb, lane));
        ldmx4(al[1], tile_addr64(aLo, mrow + 16, kb, lane));
#pragma unroll
        for (int gp = 0; gp < 4; gp += 2) {
            uint32_t b0[4], b1[4];
            ldmx4(b0, tile_addr64(bHi, ncol + gp * 16, kb, lane));
            ldmx4(b1, tile_addr64(bHi, ncol + (gp + 1) * 16, kb, lane));
#pragma unroll
            for (int mi = 0; mi < 2; ++mi) {
                mma16816(acc[mi][gp * 2 + 0], ah[mi], b0[0], b0[2]);
                mma16816(acc[mi][gp * 2 + 1], ah[mi], b0[1], b0[3]);
                mma16816(acc[mi][gp * 2 + 2], ah[mi], b1[0], b1[2]);
                mma16816(acc[mi][gp * 2 + 3], ah[mi], b1[1], b1[3]);
            }
#pragma unroll
            for (int mi = 0; mi < 2; ++mi) {
                mma16816(acc[mi][gp * 2 + 0], al[mi], b0[0], b0[2]);
                mma16816(acc[mi][gp * 2 + 1], al[mi], b0[1], b0[3]);
                mma16816(acc[mi][gp * 2 + 2], al[mi], b1[0], b1[2]);
                mma16816(acc[mi][gp * 2 + 3], al[mi], b1[1], b1[3]);
            }
            uint32_t c0[4], c1[4];
            ldmx4(c0, tile_addr64(bLo, ncol + gp * 16, kb, lane));
            ldmx4(c1, tile_addr64(bLo, ncol + (gp + 1) * 16, kb, lane));
#pragma unroll
            for (int mi = 0; mi < 2; ++mi) {
                mma16816(acc[mi][gp * 2 + 0], ah[mi], c0[0], c0[2]);
                mma16816(acc[mi][gp * 2 + 1], ah[mi], c0[1], c0[3]);
                mma16816(acc[mi][gp * 2 + 2], ah[mi], c1[0], c1[2]);
                mma16816(acc[mi][gp * 2 + 3], ah[mi], c1[1], c1[3]);
            }
        }
    }
}

#define SET32 32768   // one scores/gproj buffer set: Ahi|Alo|Bhi|Blo, 8KB each
#define TPITCH 132    // transposed spill pitch (floats)

// ---------------------------------------------------------------------------
// K1: M = W @ W^T  -> hi/lo bf16
// ---------------------------------------------------------------------------
__global__ void wwt_kernel(const float* __restrict__ W) {
    __shared__ float sR[16][257];
    __shared__ float sC[16][257];
    int tx = threadIdx.x, ty = threadIdx.y;
    int t = ty * 16 + tx;
    int r0 = blockIdx.y * 16, c0 = blockIdx.x * 16;
    {
        int row = t >> 4, base = t & 15;
#pragma unroll
        for (int p = 0; p < 16; ++p) {
            int col = base + p * 16;
            sR[row][col] = W[(r0 + row) * DD + col];
            sC[row][col] = W[(c0 + row) * DD + col];
        }
    }
    __syncthreads();
    float acc = 0.f;
#pragma unroll 8
    for (int k = 0; k < DD; ++k) acc += sR[ty][k] * sC[tx][k];
    float h, l;
    split_hl(acc, h, l);
    d_Mhi[(r0 + ty) * DD + (c0 + tx)] = __float2bfloat16(h);
    d_Mlo[(r0 + ty) * DD + (c0 + tx)] = __float2bfloat16(l);
}

// ---------------------------------------------------------------------------
// K2: X -> Xhi/Xlo (row-major) + Xthi/Xtlo ([b][d][m])
// ---------------------------------------------------------------------------
__global__ __launch_bounds__(256) void convx_kernel(const float* __restrict__ X) {
    __shared__ float tile[32][33];
    int b = blockIdx.z;
    int m0 = blockIdx.y * 32, d0 = blockIdx.x * 32;
    int j = threadIdx.x & 31, i0 = threadIdx.x >> 5;
    const float* Xb = X + (size_t)b * NN * DD;
#pragma unroll
    for (int i = i0; i < 32; i += 8) {
        float v = Xb[(size_t)(m0 + i) * DD + d0 + j];
        tile[i][j] = v;
        float h, l;
        split_hl(v, h, l);
        size_t idx = (size_t)b * NN * DD + (size_t)(m0 + i) * DD + d0 + j;
        d_Xhi[idx] = __float2bfloat16(h);
        d_Xlo[idx] = __float2bfloat16(l);
    }
    __syncthreads();
#pragma unroll
    for (int i = i0; i < 32; i += 8) {
        float v = tile[j][i];
        float h, l;
        split_hl(v, h, l);
        size_t idx = (size_t)b * DD * NN + (size_t)(d0 + i) * NN + m0 + j;
        d_Xthi[idx] = __float2bfloat16(h);
        d_Xtlo[idx] = __float2bfloat16(l);
    }
}

// ---------------------------------------------------------------------------
// K3: G = X @ M.  k32 double-buffered, occ 2 (R9 form).
// ---------------------------------------------------------------------------
__global__ __launch_bounds__(256, 2) void gproj_kernel() {
    extern __shared__ __align__(128) char sm[];
    uint32_t base = smem_to_u32(sm);
    int tid = threadIdx.x, lane = tid & 31, wid = tid >> 5;
    int nh = blockIdx.x, ti = blockIdx.y;
    int mrow = (wid >> 1) * 32, ncol = (wid & 1) * 64;

    float acc[2][8][4];
#pragma unroll
    for (int mi = 0; mi < 2; ++mi)
#pragma unroll
        for (int nf = 0; nf < 8; ++nf)
#pragma unroll
            for (int q = 0; q < 4; ++q) acc[mi][nf][q] = 0.f;

    const __nv_bfloat16* Ahi = d_Xhi + (size_t)ti * 128 * DD;
    const __nv_bfloat16* Alo = d_Xlo + (size_t)ti * 128 * DD;
    const __nv_bfloat16* Bhi = d_Mhi + nh * 128 * DD;
    const __nv_bfloat16* Blo = d_Mlo + nh * 128 * DD;

    stage32<128>(base, Ahi, DD, tid);
    stage32<128>(base + 8192, Alo, DD, tid);
    stage32<128>(base + 16384, Bhi, DD, tid);
    stage32<128>(base + 24576, Blo, DD, tid);
    CP_COMMIT();

    for (int kc = 0; kc < 8; ++kc) {
        if (kc < 7) {
            uint32_t nb = base + ((kc + 1) & 1) * SET32;
            int k0 = (kc + 1) * 32;
            stage32<128>(nb, Ahi + k0, DD, tid);
            stage32<128>(nb + 8192, Alo + k0, DD, tid);
            stage32<128>(nb + 16384, Bhi + k0, DD, tid);
            stage32<128>(nb + 24576, Blo + k0, DD, tid);
            CP_COMMIT();
            CP_WAIT(1);
        } else {
            CP_WAIT(0);
        }
        __syncthreads();
        uint32_t cb = base + (kc & 1) * SET32;
        mma_chunk3_32(acc, cb, cb + 8192, cb + 16384, cb + 24576, mrow, ncol, lane);
        __syncthreads();
    }
#pragma unroll
    for (int mi = 0; mi < 2; ++mi) {
        int rA = ti * 128 + mrow + mi * 16 + (lane >> 2);
        int rB = rA + 8;
#pragma unroll
        for (int nf = 0; nf < 8; ++nf) {
            int col = nh * 128 + ncol + nf * 8 + (lane & 3) * 2;
            float h0, l0, h1, l1;
            split_hl(acc[mi][nf][0], h0, l0);
            split_hl(acc[mi][nf][1], h1, l1);
            *(uint32_t*)&d_Ghi[(size_t)rA * DD + col] = pack_bf2(h0, h1);
            *(uint32_t*)&d_Glo[(size_t)rA * DD + col] = pack_bf2(l0, l1);
            split_hl(acc[mi][nf][2], h0, l0);
            split_hl(acc[mi][nf][3], h1, l1);
            *(uint32_t*)&d_Ghi[(size_t)rB * DD + col] = pack_bf2(h0, h1);
            *(uint32_t*)&d_Glo[(size_t)rB * DD + col] = pack_bf2(l0, l1);
        }
    }
}

// ---------------------------------------------------------------------------
// K4: scores, upper-triangle tiles, k32 double-buffered; transposed-spill
// mirror epilogue (R14, measured 248us).  Plain vectorized gmem accesses.
// ---------------------------------------------------------------------------
__global__ __launch_bounds__(256, 2) void scores_kernel(const float* __restrict__ ADJ) {
    extern __shared__ __align__(128) char sm[];
    uint32_t base = smem_to_u32(sm);
    float* sT = (float*)sm;     // transposed spill: sT[c * TPITCH + r]
    int tid = threadIdx.x, lane = tid & 31, wid = tid >> 5;
    int b = blockIdx.y;
    int rt = 0, rem = blockIdx.x;
    while (rem >= 16 - rt) { rem -= 16 - rt; rt++; }
    int nt = rt + rem;
    int mrow = (wid >> 1) * 32, ncol = (wid & 1) * 64;

    float acc[2][8][4];
#pragma unroll
    for (int mi = 0; mi < 2; ++mi)
#pragma unroll
        for (int nf = 0; nf < 8; ++nf)
#pragma unroll
            for (int q = 0; q < 4; ++q) acc[mi][nf][q] = 0.f;

    const __nv_bfloat16* Ahi = d_Ghi + ((size_t)b * NN + rt * 128) * DD;
    const __nv_bfloat16* Alo = d_Glo + ((size_t)b * NN + rt * 128) * DD;
    const __nv_bfloat16* Bhi = d_Xhi + ((size_t)b * NN + nt * 128) * DD;
    const __nv_bfloat16* Blo = d_Xlo + ((size_t)b * NN + nt * 128) * DD;

    stage32<128>(base, Ahi, DD, tid);
    stage32<128>(base + 8192, Alo, DD, tid);
    stage32<128>(base + 16384, Bhi, DD, tid);
    stage32<128>(base + 24576, Blo, DD, tid);
    CP_COMMIT();

    for (int kc = 0; kc < 8; ++kc) {
        if (kc < 7) {
            uint32_t nb = base + ((kc + 1) & 1) * SET32;
            int k0 = (kc + 1) * 32;
            stage32<128>(nb, Ahi + k0, DD, tid);
            stage32<128>(nb + 8192, Alo + k0, DD, tid);
            stage32<128>(nb + 16384, Bhi + k0, DD, tid);
            stage32<128>(nb + 24576, Blo + k0, DD, tid);
            CP_COMMIT();
            CP_WAIT(1);
        } else {
            CP_WAIT(0);
        }
        __syncthreads();
        uint32_t cb = base + (kc & 1) * SET32;
        mma_chunk3_32(acc, cb, cb + 8192, cb + 16384, cb + 24576, mrow, ncol, lane);
        __syncthreads();
    }

    // apply leaky; spill TRANSPOSED into sT[c][r] (pitch 132)
#pragma unroll
    for (int mi = 0; mi < 2; ++mi)
#pragma unroll
        for (int nf = 0; nf < 8; ++nf)
#pragma unroll
            for (int q = 0; q < 4; ++q) {
                int r = mrow + mi * 16 + (lane >> 2) + (q >> 1) * 8;
                int c = ncol + nf * 8 + (lane & 3) * 2 + (q & 1);
                float v = acc[mi][nf][q];
                v = fmaxf(v, 0.2f * v);
                acc[mi][nf][q] = v;
                sT[c * TPITCH + r] = v;
            }
    __syncthreads();

    // ---- original block: fragments -> *adj -> S + 64col partials ----
    {
        int cb0 = nt * 128 + ncol + (lane & 3) * 2;
        float mx[2][2] = {{-1e30f, -1e30f}, {-1e30f, -1e30f}};
#pragma unroll
        for (int mi = 0; mi < 2; ++mi) {
            int rA = rt * 128 + mrow + mi * 16 + (lane >> 2);
            int rB = rA + 8;
            const float* adjA = ADJ + ((size_t)b * NN + rA) * NN;
            const float* adjB = ADJ + ((size_t)b * NN + rB) * NN;
            float* swA = d_S + ((size_t)b * NN + rA) * NN;
            float* swB = d_S + ((size_t)b * NN + rB) * NN;
#pragma unroll
            for (int nf = 0; nf < 8; ++nf) {
                int c = cb0 + nf * 8;
                float2 aA = *(const float2*)&adjA[c];
                float2 aB = *(const float2*)&adjB[c];
                float v0 = acc[mi][nf][0] * aA.x;
                float v1 = acc[mi][nf][1] * aA.y;
                float v2 = acc[mi][nf][2] * aB.x;
                float v3 = acc[mi][nf][3] * aB.y;
                acc[mi][nf][0] = v0; acc[mi][nf][1] = v1;
                acc[mi][nf][2] = v2; acc[mi][nf][3] = v3;
                *(float2*)&swA[c] = make_float2(v0, v1);
                *(float2*)&swB[c] = make_float2(v2, v3);
                mx[mi][0] = fmaxf(mx[mi][0], fmaxf(v0, v1));
                mx[mi][1] = fmaxf(mx[mi][1], fmaxf(v2, v3));
            }
        }
#pragma unroll
        for (int mi = 0; mi < 2; ++mi)
#pragma unroll
            for (int h = 0; h < 2; ++h) {
                mx[mi][h] = fmaxf(mx[mi][h], __shfl_xor_sync(0xffffffffu, mx[mi][h], 1));
                mx[mi][h] = fmaxf(mx[mi][h], __shfl_xor_sync(0xffffffffu, mx[mi][h], 2));
            }
        float sum[2][2] = {{0.f, 0.f}, {0.f, 0.f}};
#pragma unroll
        for (int mi = 0; mi < 2; ++mi)
#pragma unroll
            for (int nf = 0; nf < 8; ++nf) {
                sum[mi][0] += __expf(acc[mi][nf][0] - mx[mi][0]) + __expf(acc[mi][nf][1] - mx[mi][0]);
                sum[mi][1] += __expf(acc[mi][nf][2] - mx[mi][1]) + __expf(acc[mi][nf][3] - mx[mi][1]);
            }
#pragma unroll
        for (int mi = 0; mi < 2; ++mi)
#pragma unroll
            for (int h = 0; h < 2; ++h) {
                sum[mi][h] += __shfl_xor_sync(0xffffffffu, sum[mi][h], 1);
                sum[mi][h] += __shfl_xor_sync(0xffffffffu, sum[mi][h], 2);
            }
        if ((lane & 3) == 0) {
            int pi = nt * 2 + (wid & 1);
#pragma unroll
            for (int mi = 0; mi < 2; ++mi)
#pragma unroll
                for (int h = 0; h < 2; ++h) {
                    int row = rt * 128 + mrow + mi * 16 + (lane >> 2) + h * 8;
                    size_t idx = (((size_t)b * NN + row) << 5) + pi;
                    d_pm[idx] = mx[mi][h];
                    d_pl[idx] = sum[mi][h];
                }
        }
    }

    // ---- mirror block (nt > rt): contiguous reads from transposed spill ----
    if (nt > rt) {
        int r = tid >> 1, half = tid & 1;
        int rowg = nt * 128 + r;
        const float* adjp = ADJ + ((size_t)b * NN + rowg) * NN + rt * 128 + half * 64;
        float* sp = d_S + ((size_t)b * NN + rowg) * NN + rt * 128 + half * 64;
        const float* trow = &sT[r * TPITCH + half * 64];
        float mcs[2], scs[2];
#pragma unroll
        for (int cs = 0; cs < 2; ++cs) {
            float v[32];
            float mx = -1e30f;
#pragma unroll
            for (int k = 0; k < 32; k += 4) {
                float4 a = *(const float4*)&adjp[cs * 32 + k];
                float4 sv = *(const float4*)&trow[cs * 32 + k];
                float t0 = sv.x * a.x, t1 = sv.y * a.y, t2 = sv.z * a.z, t3 = sv.w * a.w;
                v[k] = t0; v[k + 1] = t1; v[k + 2] = t2; v[k + 3] = t3;
                mx = fmaxf(mx, fmaxf(fmaxf(t0, t1), fmaxf(t2, t3)));
                *(float4*)&sp[cs * 32 + k] = make_float4(t0, t1, t2, t3);
            }
            float s = 0.f;
#pragma unroll
            for (int k = 0; k < 32; ++k) s += __expf(v[k] - mx);
            mcs[cs] = mx;
            scs[cs] = s;
        }
        float m = fmaxf(mcs[0], mcs[1]);
        float s = scs[0] * __expf(mcs[0] - m) + scs[1] * __expf(mcs[1] - m);
        size_t idx = (((size_t)(b * NN + rowg)) << 5) + rt * 2 + half;
        d_pm[idx] = m;
        d_pl[idx] = s;
    }
}

// ---------------------------------------------------------------------------
// K5: merge 32 partials -> d_rm, d_rl
// ---------------------------------------------------------------------------
__global__ void reduce_kernel() {
    int i = blockIdx.x * 256 + threadIdx.x;
    const float* pm = d_pm + ((size_t)i << 5);
    const float* pl = d_pl + ((size_t)i << 5);
    float m = -1e30f;
#pragma unroll
    for (int j = 0; j < 32; ++j) m = fmaxf(m, pm[j]);
    float l = 0.f;
#pragma unroll
    for (int j = 0; j < 32; ++j) l += pl[j] * __expf(pm[j] - m);
    d_rm[i] = m;
    d_rl[i] = l;
}

// ---------------------------------------------------------------------------
// K6: PV.  R9 form: 256 threads, k32 double-buffered, occ 2.
// Set layout: Phi 0 | Plo 4K | Xthi 8K | Xtlo 24K  (40KB/set)
// ---------------------------------------------------------------------------
__global__ __launch_bounds__(256, 2) void pv_kernel(const float* __restrict__ bias,
                                                    float* __restrict__ OUT) {
    extern __shared__ __align__(128) char smc[];
    uint32_t base = smem_to_u32(smc);
    int tid = threadIdx.x, lane = tid & 31, wid = tid >> 5;
    int rt = blockIdx.x, b = blockIdx.y;
    int mrow = (wid >> 2) * 32, ncol = (wid & 3) * 64;

    float acc[2][8][4];
#pragma unroll
    for (int mi = 0; mi < 2; ++mi)
#pragma unroll
        for (int nf = 0; nf < 8; ++nf)
#pragma unroll
            for (int q = 0; q < 4; ++q) acc[mi][nf][q] = 0.f;

    const __nv_bfloat16* Bthi = d_Xthi + (size_t)b * DD * NN;
    const __nv_bfloat16* Btlo = d_Xtlo + (size_t)b * DD * NN;

    int pr = tid >> 2, pc = (tid & 3) * 8;
    float mrw = d_rm[b * NN + rt * 64 + pr];
    float linv = 1.f / d_rl[b * NN + rt * 64 + pr];
    const float* sbase = d_S + ((size_t)b * NN + rt * 64 + pr) * NN + pc;
    uint32_t pbyte = (uint32_t)(pr * 64 + (((tid & 3) * 16) ^ (((pr >> 1) & 3) << 4)));

    // prologue: chunk 0
    stage32<256>(base + 8192, Bthi, NN, tid);
    stage32<256>(base + 24576, Btlo, NN, tid);
    CP_COMMIT();
    {
        float p[8];
        float4 s0 = *(const float4*)&sbase[0];
        float4 s1 = *(const float4*)&sbase[4];
        p[0] = __expf(s0.x - mrw) * linv; p[1] = __expf(s0.y - mrw) * linv;
        p[2] = __expf(s0.z - mrw) * linv; p[3] = __expf(s0.w - mrw) * linv;
        p[4] = __expf(s1.x - mrw) * linv; p[5] = __expf(s1.y - mrw) * linv;
        p[6] = __expf(s1.z - mrw) * linv; p[7] = __expf(s1.w - mrw) * linv;
        uint32_t hi[4], lo[4];
#pragma unroll
        for (int q = 0; q < 4; ++q) {
            float h0, l0, h1, l1;
            split_hl(p[2 * q], h0, l0);
            split_hl(p[2 * q + 1], h1, l1);
            hi[q] = pack_bf2(h0, h1);
            lo[q] = pack_bf2(l0, l1);
        }
        *(uint4*)(smc + pbyte) = make_uint4(hi[0], hi[1], hi[2], hi[3]);
        *(uint4*)(smc + 4096 + pbyte) = make_uint4(lo[0], lo[1], lo[2], lo[3]);
    }

    for (int kt = 0; kt < 64; ++kt) {
        if (kt < 63) {
            int nset = (kt + 1) & 1;
            uint32_t nb = base + nset * 40960;
            int k0 = (kt + 1) * 32;
            stage32<256>(nb + 8192, Bthi + k0, NN, tid);
            stage32<256>(nb + 24576, Btlo + k0, NN, tid);
            CP_COMMIT();
            float p[8];
            float4 s0 = *(const float4*)&sbase[k0];
            float4 s1 = *(const float4*)&sbase[k0 + 4];
            p[0] = __expf(s0.x - mrw) * linv; p[1] = __expf(s0.y - mrw) * linv;
            p[2] = __expf(s0.z - mrw) * linv; p[3] = __expf(s0.w - mrw) * linv;
            p[4] = __expf(s1.x - mrw) * linv; p[5] = __expf(s1.y - mrw) * linv;
            p[6] = __expf(s1.z - mrw) * linv; p[7] = __expf(s1.w - mrw) * linv;
            uint32_t hi[4], lo[4];
#pragma unroll
            for (int q = 0; q < 4; ++q) {
                float h0, l0, h1, l1;
                split_hl(p[2 * q], h0, l0);
                split_hl(p[2 * q + 1], h1, l1);
                hi[q] = pack_bf2(h0, h1);
                lo[q] = pack_bf2(l0, l1);
            }
            *(uint4*)(smc + nset * 40960 + pbyte) = make_uint4(hi[0], hi[1], hi[2], hi[3]);
            *(uint4*)(smc + nset * 40960 + 4096 + pbyte) = make_uint4(lo[0], lo[1], lo[2], lo[3]);
            CP_WAIT(1);
        } else {
            CP_WAIT(0);
        }
        __syncthreads();
        uint32_t cb = base + (kt & 1) * 40960;
        mma_chunk3_32(acc, cb, cb + 4096, cb + 8192, cb + 24576, mrow, ncol, lane);
        __syncthreads();
    }

#pragma unroll
    for (int mi = 0; mi < 2; ++mi) {
        int rA = rt * 64 + mrow + mi * 16 + (lane >> 2);
        int rB = rA + 8;
#pragma unroll
        for (int nf = 0; nf < 8; ++nf) {
            int col = ncol + nf * 8 + (lane & 3) * 2;
            float2 bv = *(const float2*)&bias[col];
            *(float2*)&OUT[((size_t)b * NN + rA) * DD + col] =
                make_float2(acc[mi][nf][0] + bv.x, acc[mi][nf][1] + bv.y);
            *(float2*)&OUT[((size_t)b * NN + rB) * DD + col] =
                make_float2(acc[mi][nf][2] + bv.x, acc[mi][nf][3] + bv.y);
        }
    }
}

// ---------------------------------------------------------------------------
extern "C" void kernel_launch(void* const* d_in, const int* in_sizes, int n_in,
                              void* d_out, int out_size) {
    const float* x    = (const float*)d_in[0];
    const float* adj  = (const float*)d_in[1];
    const float* W    = (const float*)d_in[2];
    const float* bias = (const float*)d_in[3];
    float* out = (float*)d_out;

    wwt_kernel<<<dim3(16, 16), dim3(16, 16)>>>(W);
    convx_kernel<<<dim3(8, 64, 16), 256>>>(x);

    const int SMB_G = 2 * SET32;                 // 65536
    const int SMB_S = 128 * TPITCH * 4;          // 67584 (holds buffers + sT)
    const int SMB_P = 81920;                     // 2 x 40KB
    cudaFuncSetAttribute(gproj_kernel, cudaFuncAttributeMaxDynamicSharedMemorySize, SMB_G);
    cudaFuncSetAttribute(scores_kernel, cudaFuncAttributeMaxDynamicSharedMemorySize, SMB_S);
    cudaFuncSetAttribute(pv_kernel, cudaFuncAttributeMaxDynamicSharedMemorySize, SMB_P);

    gproj_kernel<<<dim3(2, 256), 256, SMB_G>>>();
    scores_kernel<<<dim3(136, 16), 256, SMB_S>>>(adj);
    reduce_kernel<<<BATCH * NN / 256, 256>>>();
    pv_kernel<<<dim3(32, 16), 256, SMB_P>>>(bias, out);
}